// round 3
// baseline (speedup 1.0000x reference)
#include <cuda_runtime.h>

// Problem constants (B=8, S=512 -> N=4096 tokens)
#define N_TOK   4096
#define H_DIM   512
#define E_DIM   512
#define V_DIM   32000
#define DEPTH_EMBED_SCALE 0.01f
#define SIB_SCALE_F 0.04419417382415922f   // (float)(1/sqrt(512))

// Scratch (no allocations allowed -> __device__ globals)
__device__ float g_h0[N_TOK * H_DIM];            // depth-0 node
__device__ float g_c1[N_TOK * 2 * H_DIM];        // depth-1 nodes (2 per token)
__device__ float g_c2[N_TOK * 4 * H_DIM];        // depth-2 nodes (4 per token)
__device__ float g_c3[N_TOK * 8 * H_DIM];        // depth-3 nodes (8 per token)
__device__ float g_pooled[N_TOK * H_DIM];

// ---------------------------------------------------------------------------
// Tiled fp32 SGEMM: C[M,Ncol] = A[M,K] @ B[K,Ncol] + bias (+ sib epilogue)
// Tile 128x128, BK=8, 256 threads, 8x8 per-thread micro-tile.
// gather != nullptr: A row r is A[gather[r]] (embedding gather).
// EPI==1: also add SIB_SCALE * sib[c] (c < 1024; sib is (2,512) flattened, and
//         column c of the child GEMM maps exactly to sib_flat[c]).
// All dims are multiples of tile sizes for this problem (no bounds checks).
// ---------------------------------------------------------------------------
template<int EPI>
__global__ __launch_bounds__(256, 2)
void sgemm128(const float* __restrict__ A, const float* __restrict__ B,
              float* __restrict__ C, int M, int Ncol, int K,
              const float* __restrict__ bias, const float* __restrict__ sib,
              const int* __restrict__ gather)
{
    __shared__ float As[8][128];
    __shared__ float Bs[8][128];
    const int tid  = threadIdx.x;
    const int row0 = blockIdx.y * 128;
    const int col0 = blockIdx.x * 128;

    // A-tile load mapping: 2 threads per row, float4 along K
    const int arow = tid >> 1;
    const int akk  = (tid & 1) << 2;
    // B-tile load mapping: 32 threads per k-row, float4 along N
    const int bk   = tid >> 5;
    const int bcol = (tid & 31) << 2;
    // compute mapping: 16x16 thread grid, 8x8 each
    const int tx = tid & 15;
    const int ty = tid >> 4;

    const float* Arow;
    {
        int r = row0 + arow;
        size_t rr = gather ? (size_t)gather[r] : (size_t)r;
        Arow = A + rr * (size_t)K;
    }
    const float* Bp = B + (size_t)bk * (size_t)Ncol + col0 + bcol;

    float acc[8][8];
    #pragma unroll
    for (int i = 0; i < 8; i++)
        #pragma unroll
        for (int j = 0; j < 8; j++) acc[i][j] = 0.f;

    for (int k0 = 0; k0 < K; k0 += 8) {
        float4 av = *(const float4*)(Arow + k0 + akk);
        As[akk + 0][arow] = av.x;
        As[akk + 1][arow] = av.y;
        As[akk + 2][arow] = av.z;
        As[akk + 3][arow] = av.w;
        float4 bv = *(const float4*)(Bp + (size_t)k0 * (size_t)Ncol);
        *(float4*)&Bs[bk][bcol] = bv;
        __syncthreads();
        #pragma unroll
        for (int k = 0; k < 8; k++) {
            float a[8], b[8];
            *(float4*)&a[0] = *(const float4*)&As[k][ty * 8];
            *(float4*)&a[4] = *(const float4*)&As[k][ty * 8 + 4];
            *(float4*)&b[0] = *(const float4*)&Bs[k][tx * 8];
            *(float4*)&b[4] = *(const float4*)&Bs[k][tx * 8 + 4];
            #pragma unroll
            for (int i = 0; i < 8; i++)
                #pragma unroll
                for (int j = 0; j < 8; j++)
                    acc[i][j] = fmaf(a[i], b[j], acc[i][j]);
        }
        __syncthreads();
    }

    // Epilogue: bias (+ sib) then vectorized store
    const int cbase = col0 + tx * 8;
    float badd[8];
    #pragma unroll
    for (int j = 0; j < 8; j++) {
        float v = bias[cbase + j];
        if (EPI == 1) v += SIB_SCALE_F * sib[cbase + j];
        badd[j] = v;
    }
    #pragma unroll
    for (int i = 0; i < 8; i++) {
        int r = row0 + ty * 8 + i;
        float* Cp = C + (size_t)r * (size_t)Ncol + cbase;
        float4 o0, o1;
        o0.x = acc[i][0] + badd[0];
        o0.y = acc[i][1] + badd[1];
        o0.z = acc[i][2] + badd[2];
        o0.w = acc[i][3] + badd[3];
        o1.x = acc[i][4] + badd[4];
        o1.y = acc[i][5] + badd[5];
        o1.z = acc[i][6] + badd[6];
        o1.w = acc[i][7] + badd[7];
        *(float4*)(Cp + 0) = o0;
        *(float4*)(Cp + 4) = o1;
    }
}

// ---------------------------------------------------------------------------
// Gate + pool kernel: one block (256 thr) per token.
// Gates (fp32, reference-faithful): g = dot(node + 0.01*dep[d], Wg) + bg.
// expand iff g > 0 (sigmoid(g) > 0.5, clip is irrelevant to the threshold).
// pooled = (h0 + sum of active children at depths 1..3) / count.
// ---------------------------------------------------------------------------
__global__ __launch_bounds__(256)
void pool_kernel(const float* __restrict__ Wg, const float* __restrict__ bgp,
                 const float* __restrict__ dep, float* __restrict__ pooled)
{
    const int n = blockIdx.x;
    const int t = threadIdx.x;
    const float* H0 = g_h0 + (size_t)n * H_DIM;
    const float* C1 = g_c1 + (size_t)n * (2 * H_DIM);
    const float* C2 = g_c2 + (size_t)n * (4 * H_DIM);
    const float* C3 = g_c3 + (size_t)n * (8 * H_DIM);

    __shared__ float red[7][256];
    float p[7] = {0.f, 0.f, 0.f, 0.f, 0.f, 0.f, 0.f};
    for (int c = t; c < H_DIM; c += 256) {
        float w  = Wg[c];
        float d0 = DEPTH_EMBED_SCALE * dep[c];
        float d1 = DEPTH_EMBED_SCALE * dep[H_DIM + c];
        float d2 = DEPTH_EMBED_SCALE * dep[2 * H_DIM + c];
        p[0] += (H0[c] + d0) * w;
        p[1] += (C1[c] + d1) * w;
        p[2] += (C1[H_DIM + c] + d1) * w;
        p[3] += (C2[0 * H_DIM + c] + d2) * w;
        p[4] += (C2[1 * H_DIM + c] + d2) * w;
        p[5] += (C2[2 * H_DIM + c] + d2) * w;
        p[6] += (C2[3 * H_DIM + c] + d2) * w;
    }
    #pragma unroll
    for (int g = 0; g < 7; g++) red[g][t] = p[g];
    __syncthreads();
    for (int s = 128; s > 0; s >>= 1) {
        if (t < s) {
            #pragma unroll
            for (int g = 0; g < 7; g++) red[g][t] += red[g][t + s];
        }
        __syncthreads();
    }

    const float bg0 = bgp[0];
    const bool e0 = (red[0][0] + bg0) > 0.f;
    bool e1[2], e2[4];
    e1[0] = e0 && ((red[1][0] + bg0) > 0.f);
    e1[1] = e0 && ((red[2][0] + bg0) > 0.f);
    e2[0] = e1[0] && ((red[3][0] + bg0) > 0.f);
    e2[1] = e1[0] && ((red[4][0] + bg0) > 0.f);
    e2[2] = e1[1] && ((red[5][0] + bg0) > 0.f);
    e2[3] = e1[1] && ((red[6][0] + bg0) > 0.f);

    float count = 1.f
        + 2.f * (e0 ? 1.f : 0.f)
        + 2.f * ((e1[0] ? 1.f : 0.f) + (e1[1] ? 1.f : 0.f))
        + 2.f * ((e2[0] ? 1.f : 0.f) + (e2[1] ? 1.f : 0.f) +
                 (e2[2] ? 1.f : 0.f) + (e2[3] ? 1.f : 0.f));
    const float inv = 1.f / fmaxf(count, 1e-8f);

    for (int c = t; c < H_DIM; c += 256) {
        float s = H0[c];
        if (e0)    s += C1[c] + C1[H_DIM + c];
        if (e1[0]) s += C2[c] + C2[H_DIM + c];
        if (e1[1]) s += C2[2 * H_DIM + c] + C2[3 * H_DIM + c];
        if (e2[0]) s += C3[0 * H_DIM + c] + C3[1 * H_DIM + c];
        if (e2[1]) s += C3[2 * H_DIM + c] + C3[3 * H_DIM + c];
        if (e2[2]) s += C3[4 * H_DIM + c] + C3[5 * H_DIM + c];
        if (e2[3]) s += C3[6 * H_DIM + c] + C3[7 * H_DIM + c];
        pooled[(size_t)n * H_DIM + c] = s * inv;
    }
}

// ---------------------------------------------------------------------------
extern "C" void kernel_launch(void* const* d_in, const int* in_sizes, int n_in,
                              void* d_out, int out_size)
{
    const int*   tokens = (const int*)  d_in[0];
    const float* emb    = (const float*)d_in[1];
    const float* Wp     = (const float*)d_in[2];
    const float* bp     = (const float*)d_in[3];
    const float* Wc     = (const float*)d_in[4];
    const float* bc     = (const float*)d_in[5];
    const float* Wg     = (const float*)d_in[6];
    const float* bg     = (const float*)d_in[7];
    const float* dep    = (const float*)d_in[8];
    const float* sib    = (const float*)d_in[9];
    const float* Wout   = (const float*)d_in[10];
    const float* bout   = (const float*)d_in[11];
    float* out = (float*)d_out;

    float *h0, *c1, *c2, *c3, *pooled;
    cudaGetSymbolAddress((void**)&h0,     g_h0);
    cudaGetSymbolAddress((void**)&c1,     g_c1);
    cudaGetSymbolAddress((void**)&c2,     g_c2);
    cudaGetSymbolAddress((void**)&c3,     g_c3);
    cudaGetSymbolAddress((void**)&pooled, g_pooled);

    dim3 blk(256);

    // h0 = emb[tokens] @ Wp + bp        (4096 x 512 x 512, gathered A)
    sgemm128<0><<<dim3(H_DIM / 128, N_TOK / 128), blk>>>(
        emb, Wp, h0, N_TOK, H_DIM, E_DIM, bp, nullptr, tokens);

    // depth-1 children: (4096 x 512) @ (512 x 1024) + bc + SIB*sib
    sgemm128<1><<<dim3(1024 / 128, N_TOK / 128), blk>>>(
        h0, Wc, c1, N_TOK, 1024, H_DIM, bc, sib, nullptr);

    // depth-2 children: (8192 x 512) @ (512 x 1024)
    sgemm128<1><<<dim3(1024 / 128, (2 * N_TOK) / 128), blk>>>(
        c1, Wc, c2, 2 * N_TOK, 1024, H_DIM, bc, sib, nullptr);

    // depth-3 children: (16384 x 512) @ (512 x 1024)
    sgemm128<1><<<dim3(1024 / 128, (4 * N_TOK) / 128), blk>>>(
        c2, Wc, c3, 4 * N_TOK, 1024, H_DIM, bc, sib, nullptr);

    // gates + masked pooling
    pool_kernel<<<N_TOK, blk>>>(Wg, bg, dep, pooled);

    // logits = pooled @ Wout + bout     (4096 x 32000 x 512)
    sgemm128<0><<<dim3(V_DIM / 128, N_TOK / 128), blk>>>(
        pooled, Wout, out, N_TOK, V_DIM, H_DIM, bout, nullptr, nullptr);
}

// round 4
// speedup vs baseline: 2.4633x; 2.4633x over previous
#include <cuda_runtime.h>
#include <cstdint>

// Problem constants (B=8, S=512 -> N=4096 tokens)
#define N_TOK   4096
#define H_DIM   512
#define E_DIM   512
#define V_DIM   32000
#define DEPTH_EMBED_SCALE 0.01f
#define SIB_SCALE_F 0.04419417382415922f   // (float)(1/sqrt(512))

// Scratch (no allocations allowed -> __device__ globals)
__device__ float g_h0[N_TOK * H_DIM];            // depth-0 node
__device__ float g_c1[N_TOK * 2 * H_DIM];        // depth-1 nodes (2 per token)
__device__ float g_c2[N_TOK * 4 * H_DIM];        // depth-2 nodes (4 per token)
__device__ float g_d3[N_TOK * 4 * H_DIM];        // depth-3 PAIR SUMS (c2_k @ W2 + b2)
__device__ float g_pooled[N_TOK * H_DIM];
__device__ float g_W2[H_DIM * H_DIM];            // WcL + WcR
__device__ float g_b2[H_DIM];                    // bcL + bcR + SIB*(sib0+sib1)

// ---------------------------------------------------------------------------
// Tiny prep: W2[h][j] = Wc[h][j] + Wc[h][512+j];  b2[j] = bc[j]+bc[512+j]+SIB*(sib[j]+sib[512+j])
// ---------------------------------------------------------------------------
__global__ void prep_w2(const float* __restrict__ Wc, const float* __restrict__ bc,
                        const float* __restrict__ sib)
{
    int i = blockIdx.x * 256 + threadIdx.x;        // 0 .. 512*512-1
    int h = i >> 9, j = i & 511;
    g_W2[i] = Wc[(size_t)h * 1024 + j] + Wc[(size_t)h * 1024 + 512 + j];
    if (i < H_DIM)
        g_b2[i] = bc[i] + bc[512 + i] + SIB_SCALE_F * (sib[i] + sib[512 + i]);
}

// ---------------------------------------------------------------------------
// Tiled fp32 SGEMM (exact path for anything that feeds gate decisions).
// C[M,Ncol] = A[M,K] @ B[K,Ncol] + bias (+ sib epilogue). 128x128x8, 256 thr.
// ---------------------------------------------------------------------------
template<int EPI>
__global__ __launch_bounds__(256, 2)
void sgemm128(const float* __restrict__ A, const float* __restrict__ B,
              float* __restrict__ C, int M, int Ncol, int K,
              const float* __restrict__ bias, const float* __restrict__ sib,
              const int* __restrict__ gather)
{
    __shared__ float As[8][128];
    __shared__ float Bs[8][128];
    const int tid  = threadIdx.x;
    const int row0 = blockIdx.y * 128;
    const int col0 = blockIdx.x * 128;

    const int arow = tid >> 1;
    const int akk  = (tid & 1) << 2;
    const int bk   = tid >> 5;
    const int bcol = (tid & 31) << 2;
    const int tx = tid & 15;
    const int ty = tid >> 4;

    const float* Arow;
    {
        int r = row0 + arow;
        size_t rr = gather ? (size_t)gather[r] : (size_t)r;
        Arow = A + rr * (size_t)K;
    }
    const float* Bp = B + (size_t)bk * (size_t)Ncol + col0 + bcol;

    float acc[8][8];
    #pragma unroll
    for (int i = 0; i < 8; i++)
        #pragma unroll
        for (int j = 0; j < 8; j++) acc[i][j] = 0.f;

    for (int k0 = 0; k0 < K; k0 += 8) {
        float4 av = *(const float4*)(Arow + k0 + akk);
        As[akk + 0][arow] = av.x;
        As[akk + 1][arow] = av.y;
        As[akk + 2][arow] = av.z;
        As[akk + 3][arow] = av.w;
        float4 bv = *(const float4*)(Bp + (size_t)k0 * (size_t)Ncol);
        *(float4*)&Bs[bk][bcol] = bv;
        __syncthreads();
        #pragma unroll
        for (int k = 0; k < 8; k++) {
            float a[8], b[8];
            *(float4*)&a[0] = *(const float4*)&As[k][ty * 8];
            *(float4*)&a[4] = *(const float4*)&As[k][ty * 8 + 4];
            *(float4*)&b[0] = *(const float4*)&Bs[k][tx * 8];
            *(float4*)&b[4] = *(const float4*)&Bs[k][tx * 8 + 4];
            #pragma unroll
            for (int i = 0; i < 8; i++)
                #pragma unroll
                for (int j = 0; j < 8; j++)
                    acc[i][j] = fmaf(a[i], b[j], acc[i][j]);
        }
        __syncthreads();
    }

    const int cbase = col0 + tx * 8;
    float badd[8];
    #pragma unroll
    for (int j = 0; j < 8; j++) {
        float v = bias[cbase + j];
        if (EPI == 1) v += SIB_SCALE_F * sib[cbase + j];
        badd[j] = v;
    }
    #pragma unroll
    for (int i = 0; i < 8; i++) {
        int r = row0 + ty * 8 + i;
        float* Cp = C + (size_t)r * (size_t)Ncol + cbase;
        float4 o0, o1;
        o0.x = acc[i][0] + badd[0];
        o0.y = acc[i][1] + badd[1];
        o0.z = acc[i][2] + badd[2];
        o0.w = acc[i][3] + badd[3];
        o1.x = acc[i][4] + badd[4];
        o1.y = acc[i][5] + badd[5];
        o1.z = acc[i][6] + badd[6];
        o1.w = acc[i][7] + badd[7];
        *(float4*)(Cp + 0) = o0;
        *(float4*)(Cp + 4) = o1;
    }
}

// ---------------------------------------------------------------------------
// tf32 tensor-core GEMM: C = A @ B + bias.  128x128 tile, BK=16, 256 threads,
// 8 warps in 2x4, warp tile 64x32, mma.sync.m16n8k8.tf32, double-buffered
// cp.async. A row-major (lda=K), B row-major (ldb=Ncol). No bounds checks
// (all dims divide tiles for this problem).
// ---------------------------------------------------------------------------
#define AS_LD 20     // BK(16) + 4 pad -> conflict-free a-frag LDS
#define BS_LD 136    // BN(128) + 8 pad -> conflict-free b-frag LDS

__device__ __forceinline__ void cp16(void* s, const void* g) {
    unsigned saddr = (unsigned)__cvta_generic_to_shared(s);
    asm volatile("cp.async.cg.shared.global [%0], [%1], 16;\n" :: "r"(saddr), "l"(g));
}
__device__ __forceinline__ uint32_t f2tf32(float v) {
    uint32_t r;
    asm("cvt.rna.tf32.f32 %0, %1;" : "=r"(r) : "f"(v));
    return r;
}

__global__ __launch_bounds__(256, 2)
void gemm_tf32(const float* __restrict__ A, const float* __restrict__ B,
               float* __restrict__ C, int M, int Ncol, int K,
               const float* __restrict__ bias)
{
    __shared__ float As[2][128][AS_LD];
    __shared__ float Bs[2][16][BS_LD];

    const int tid  = threadIdx.x;
    const int row0 = blockIdx.y * 128;
    const int col0 = blockIdx.x * 128;
    const int warp = tid >> 5, lane = tid & 31;
    const int gid  = lane >> 2, tg = lane & 3;
    const int wm   = (warp & 1) * 64;
    const int wn   = (warp >> 1) * 32;

    // cp.async load mapping
    const int ar = tid >> 1;           // A row 0..127
    const int ak = (tid & 1) * 8;      // A k base: 0 or 8 (two 16B chunks each)
    const int br = tid >> 4;           // B k-row 0..15
    const int bcg = (tid & 15) * 4;    // B col base (two chunks: +0, +64)

    const float* Ag = A + (size_t)(row0 + ar) * (size_t)K + ak;
    const float* Bg = B + (size_t)br * (size_t)Ncol + col0 + bcg;

    float acc[4][4][4];
    #pragma unroll
    for (int mi = 0; mi < 4; mi++)
        #pragma unroll
        for (int ni = 0; ni < 4; ni++)
            #pragma unroll
            for (int q = 0; q < 4; q++) acc[mi][ni][q] = 0.f;

    const int NT = K / 16;

    // prefetch tile 0
    {
        cp16(&As[0][ar][ak],     Ag);
        cp16(&As[0][ar][ak + 4], Ag + 4);
        cp16(&Bs[0][br][bcg],      Bg);
        cp16(&Bs[0][br][bcg + 64], Bg + 64);
        asm volatile("cp.async.commit_group;\n");
    }

    for (int kt = 0; kt < NT; kt++) {
        const int cur = kt & 1;
        if (kt + 1 < NT) {
            const float* Agn = Ag + (size_t)(kt + 1) * 16;
            const float* Bgn = Bg + (size_t)(kt + 1) * 16 * (size_t)Ncol;
            cp16(&As[cur ^ 1][ar][ak],     Agn);
            cp16(&As[cur ^ 1][ar][ak + 4], Agn + 4);
            cp16(&Bs[cur ^ 1][br][bcg],      Bgn);
            cp16(&Bs[cur ^ 1][br][bcg + 64], Bgn + 64);
            asm volatile("cp.async.commit_group;\n");
            asm volatile("cp.async.wait_group 1;\n");
        } else {
            asm volatile("cp.async.wait_group 0;\n");
        }
        __syncthreads();

        #pragma unroll
        for (int ks = 0; ks < 2; ks++) {
            const int kk = ks * 8;
            uint32_t af[4][4];
            #pragma unroll
            for (int mi = 0; mi < 4; mi++) {
                int r = wm + mi * 16 + gid;
                af[mi][0] = f2tf32(As[cur][r    ][kk + tg]);
                af[mi][1] = f2tf32(As[cur][r + 8][kk + tg]);
                af[mi][2] = f2tf32(As[cur][r    ][kk + tg + 4]);
                af[mi][3] = f2tf32(As[cur][r + 8][kk + tg + 4]);
            }
            uint32_t bf[4][2];
            #pragma unroll
            for (int ni = 0; ni < 4; ni++) {
                int cc = wn + ni * 8 + gid;
                bf[ni][0] = f2tf32(Bs[cur][kk + tg    ][cc]);
                bf[ni][1] = f2tf32(Bs[cur][kk + tg + 4][cc]);
            }
            #pragma unroll
            for (int mi = 0; mi < 4; mi++)
                #pragma unroll
                for (int ni = 0; ni < 4; ni++) {
                    asm volatile(
                        "mma.sync.aligned.m16n8k8.row.col.f32.tf32.tf32.f32 "
                        "{%0,%1,%2,%3}, {%4,%5,%6,%7}, {%8,%9}, {%0,%1,%2,%3};"
                        : "+f"(acc[mi][ni][0]), "+f"(acc[mi][ni][1]),
                          "+f"(acc[mi][ni][2]), "+f"(acc[mi][ni][3])
                        : "r"(af[mi][0]), "r"(af[mi][1]), "r"(af[mi][2]), "r"(af[mi][3]),
                          "r"(bf[ni][0]), "r"(bf[ni][1]));
                }
        }
        __syncthreads();
    }

    // Epilogue: C[gid][tg*2 .. +1] and C[gid+8][...] per 16x8 frag, + bias
    #pragma unroll
    for (int ni = 0; ni < 4; ni++) {
        int cc = col0 + wn + ni * 8 + tg * 2;
        float b0 = bias[cc], b1 = bias[cc + 1];
        #pragma unroll
        for (int mi = 0; mi < 4; mi++) {
            int r = row0 + wm + mi * 16 + gid;
            float2 v0 = make_float2(acc[mi][ni][0] + b0, acc[mi][ni][1] + b1);
            float2 v1 = make_float2(acc[mi][ni][2] + b0, acc[mi][ni][3] + b1);
            *(float2*)(C + (size_t)r * (size_t)Ncol + cc)       = v0;
            *(float2*)(C + (size_t)(r + 8) * (size_t)Ncol + cc) = v1;
        }
    }
}

// ---------------------------------------------------------------------------
// Gate + pool kernel: one block (256 thr) per token. Gates exact fp32.
// Depth-3 contribution comes from precomputed pair sums g_d3 (exact algebra).
// ---------------------------------------------------------------------------
__global__ __launch_bounds__(256)
void pool_kernel(const float* __restrict__ Wg, const float* __restrict__ bgp,
                 const float* __restrict__ dep, float* __restrict__ pooled)
{
    const int n = blockIdx.x;
    const int t = threadIdx.x;
    const float* H0 = g_h0 + (size_t)n * H_DIM;
    const float* C1 = g_c1 + (size_t)n * (2 * H_DIM);
    const float* C2 = g_c2 + (size_t)n * (4 * H_DIM);
    const float* D3 = g_d3 + (size_t)n * (4 * H_DIM);

    __shared__ float red[7][256];
    float p[7] = {0.f, 0.f, 0.f, 0.f, 0.f, 0.f, 0.f};
    for (int c = t; c < H_DIM; c += 256) {
        float w  = Wg[c];
        float d0 = DEPTH_EMBED_SCALE * dep[c];
        float d1 = DEPTH_EMBED_SCALE * dep[H_DIM + c];
        float d2 = DEPTH_EMBED_SCALE * dep[2 * H_DIM + c];
        p[0] += (H0[c] + d0) * w;
        p[1] += (C1[c] + d1) * w;
        p[2] += (C1[H_DIM + c] + d1) * w;
        p[3] += (C2[0 * H_DIM + c] + d2) * w;
        p[4] += (C2[1 * H_DIM + c] + d2) * w;
        p[5] += (C2[2 * H_DIM + c] + d2) * w;
        p[6] += (C2[3 * H_DIM + c] + d2) * w;
    }
    #pragma unroll
    for (int g = 0; g < 7; g++) red[g][t] = p[g];
    __syncthreads();
    for (int s = 128; s > 0; s >>= 1) {
        if (t < s) {
            #pragma unroll
            for (int g = 0; g < 7; g++) red[g][t] += red[g][t + s];
        }
        __syncthreads();
    }

    const float bg0 = bgp[0];
    const bool e0 = (red[0][0] + bg0) > 0.f;
    bool e1[2], e2[4];
    e1[0] = e0 && ((red[1][0] + bg0) > 0.f);
    e1[1] = e0 && ((red[2][0] + bg0) > 0.f);
    e2[0] = e1[0] && ((red[3][0] + bg0) > 0.f);
    e2[1] = e1[0] && ((red[4][0] + bg0) > 0.f);
    e2[2] = e1[1] && ((red[5][0] + bg0) > 0.f);
    e2[3] = e1[1] && ((red[6][0] + bg0) > 0.f);

    float count = 1.f
        + 2.f * (e0 ? 1.f : 0.f)
        + 2.f * ((e1[0] ? 1.f : 0.f) + (e1[1] ? 1.f : 0.f))
        + 2.f * ((e2[0] ? 1.f : 0.f) + (e2[1] ? 1.f : 0.f) +
                 (e2[2] ? 1.f : 0.f) + (e2[3] ? 1.f : 0.f));
    const float inv = 1.f / fmaxf(count, 1e-8f);

    for (int c = t; c < H_DIM; c += 256) {
        float s = H0[c];
        if (e0)    s += C1[c] + C1[H_DIM + c];
        if (e1[0]) s += C2[c] + C2[H_DIM + c];
        if (e1[1]) s += C2[2 * H_DIM + c] + C2[3 * H_DIM + c];
        if (e2[0]) s += D3[0 * H_DIM + c];
        if (e2[1]) s += D3[1 * H_DIM + c];
        if (e2[2]) s += D3[2 * H_DIM + c];
        if (e2[3]) s += D3[3 * H_DIM + c];
        pooled[(size_t)n * H_DIM + c] = s * inv;
    }
}

// ---------------------------------------------------------------------------
extern "C" void kernel_launch(void* const* d_in, const int* in_sizes, int n_in,
                              void* d_out, int out_size)
{
    const int*   tokens = (const int*)  d_in[0];
    const float* emb    = (const float*)d_in[1];
    const float* Wp     = (const float*)d_in[2];
    const float* bp     = (const float*)d_in[3];
    const float* Wc     = (const float*)d_in[4];
    const float* bc     = (const float*)d_in[5];
    const float* Wg     = (const float*)d_in[6];
    const float* bg     = (const float*)d_in[7];
    const float* dep    = (const float*)d_in[8];
    const float* sib    = (const float*)d_in[9];
    const float* Wout   = (const float*)d_in[10];
    const float* bout   = (const float*)d_in[11];
    float* out = (float*)d_out;

    float *h0, *c1, *c2, *d3, *pooled, *W2, *b2;
    cudaGetSymbolAddress((void**)&h0,     g_h0);
    cudaGetSymbolAddress((void**)&c1,     g_c1);
    cudaGetSymbolAddress((void**)&c2,     g_c2);
    cudaGetSymbolAddress((void**)&d3,     g_d3);
    cudaGetSymbolAddress((void**)&pooled, g_pooled);
    cudaGetSymbolAddress((void**)&W2,     g_W2);
    cudaGetSymbolAddress((void**)&b2,     g_b2);

    dim3 blk(256);

    // W2 = WcL + WcR,  b2 = bcL + bcR + SIB*(sib0+sib1)
    prep_w2<<<(H_DIM * H_DIM) / 256, blk>>>(Wc, bc, sib);

    // h0 = emb[tokens] @ Wp + bp        (4096 x 512 x 512, gathered A) — exact fp32
    sgemm128<0><<<dim3(H_DIM / 128, N_TOK / 128), blk>>>(
        emb, Wp, h0, N_TOK, H_DIM, E_DIM, bp, nullptr, tokens);

    // depth-1 children (exact fp32: feeds gates)
    sgemm128<1><<<dim3(1024 / 128, N_TOK / 128), blk>>>(
        h0, Wc, c1, N_TOK, 1024, H_DIM, bc, sib, nullptr);

    // depth-2 children (exact fp32: feeds gates)
    sgemm128<1><<<dim3(1024 / 128, (2 * N_TOK) / 128), blk>>>(
        c1, Wc, c2, 2 * N_TOK, 1024, H_DIM, bc, sib, nullptr);

    // depth-3 PAIR SUMS: d3 = c2 @ W2 + b2  (16384 x 512 x 512) — exact algebra
    sgemm128<0><<<dim3(H_DIM / 128, (4 * N_TOK) / 128), blk>>>(
        c2, W2, d3, 4 * N_TOK, H_DIM, H_DIM, b2, nullptr, nullptr);

    // gates + masked pooling (gates in exact fp32)
    pool_kernel<<<N_TOK, blk>>>(Wg, bg, dep, pooled);

    // logits = pooled @ Wout + bout  (4096 x 32000 x 512) — tf32 tensor cores
    gemm_tf32<<<dim3(V_DIM / 128, N_TOK / 128), blk>>>(
        pooled, Wout, out, N_TOK, V_DIM, H_DIM, bout);
}

// round 6
// speedup vs baseline: 2.8351x; 1.1509x over previous
#include <cuda_runtime.h>
#include <cstdint>

// Problem constants (B=8, S=512 -> N=4096 tokens)
#define N_TOK   4096
#define H_DIM   512
#define V_DIM   32000
#define DEPTH_EMBED_SCALE 0.01f
#define SIB_SCALE_F 0.04419417382415922f   // (float)(1/sqrt(512))

// Scratch (no allocations -> __device__ globals)
__device__ float g_h0[N_TOK * H_DIM];
__device__ float g_c1[N_TOK * 2 * H_DIM];
__device__ float g_c2[N_TOK * 4 * H_DIM];
__device__ float g_d3[N_TOK * 4 * H_DIM];        // depth-3 pair sums = c2 @ W2 + b2
__device__ float g_pooled[N_TOK * H_DIM];
__device__ float g_W2[H_DIM * H_DIM];            // round_tf32(WcL + WcR)
__device__ float g_b2[H_DIM];
__device__ float g_Wc_r[H_DIM * 1024];           // tf32-rounded Wc
__device__ float g_Wout_r[H_DIM * V_DIM];        // tf32-rounded Wout
// Gate composite precompute
__device__ float  g_uL[H_DIM], g_uR[H_DIM], g_bL[H_DIM], g_bR[H_DIM];
__device__ float  g_cols[7][H_DIM];              // gate vectors in h0-space
__device__ float  g_GG[7][H_DIM];                // gate vectors in emb-space (Wp @ cols)
__device__ double g_kc[7];                       // gate scalar constants
__device__ double g_dots[16];

__device__ __forceinline__ uint32_t f2tf32(float v) {
    uint32_t r;
    asm("cvt.rna.tf32.f32 %0, %1;" : "=r"(r) : "f"(v));
    return r;
}
__device__ __forceinline__ float rtf(float v) { return __uint_as_float(f2tf32(v)); }
__device__ __forceinline__ void cp16(void* s, const void* g) {
    unsigned saddr = (unsigned)__cvta_generic_to_shared(s);
    asm volatile("cp.async.cg.shared.global [%0], [%1], 16;\n" :: "r"(saddr), "l"(g));
}

// ---------------------------------------------------------------------------
// Prep kernels
// ---------------------------------------------------------------------------
__global__ void round_tf32_k(const float* __restrict__ src, float* __restrict__ dst, int n4)
{
    int i = blockIdx.x * 256 + threadIdx.x;
    if (i < n4) {
        float4 v = ((const float4*)src)[i];
        v.x = rtf(v.x); v.y = rtf(v.y); v.z = rtf(v.z); v.w = rtf(v.w);
        ((float4*)dst)[i] = v;
    }
}

__global__ void prep_w2(const float* __restrict__ Wc, const float* __restrict__ bc,
                        const float* __restrict__ sib)
{
    int i = blockIdx.x * 256 + threadIdx.x;   // 0 .. 512*512-1
    int h = i >> 9, j = i & 511;
    g_W2[i] = rtf(Wc[(size_t)h * 1024 + j] + Wc[(size_t)h * 1024 + 512 + j]);
    if (i < H_DIM)
        g_b2[i] = bc[i] + bc[512 + i] + SIB_SCALE_F * (sib[i] + sib[512 + i]);
}

// uL = WcL@Wg, uR = WcR@Wg; bL/bR vectors. grid=512 blocks x 128 thr.
__global__ void prep_g1(const float* __restrict__ Wc, const float* __restrict__ Wg,
                        const float* __restrict__ bc, const float* __restrict__ sib)
{
    const int h = blockIdx.x, t = threadIdx.x;
    __shared__ double s[2][128];
    double aL = 0.0, aR = 0.0;
    for (int j = t; j < H_DIM; j += 128) {
        double w = (double)Wg[j];
        aL += (double)Wc[(size_t)h * 1024 + j]       * w;
        aR += (double)Wc[(size_t)h * 1024 + 512 + j] * w;
    }
    s[0][t] = aL; s[1][t] = aR;
    __syncthreads();
    for (int st = 64; st > 0; st >>= 1) {
        if (t < st) { s[0][t] += s[0][t + st]; s[1][t] += s[1][t + st]; }
        __syncthreads();
    }
    if (t == 0) {
        g_uL[h] = (float)s[0][0];
        g_uR[h] = (float)s[1][0];
        g_bL[h] = bc[h]       + SIB_SCALE_F * sib[h];
        g_bR[h] = bc[512 + h] + SIB_SCALE_F * sib[512 + h];
    }
}

// cols[3..6] = {WcL@uL, WcL@uR, WcR@uL, WcR@uR}; cols[0..2] = {Wg, uL, uR}.
__global__ void prep_g2(const float* __restrict__ Wc, const float* __restrict__ Wg)
{
    const int h = blockIdx.x, t = threadIdx.x;
    __shared__ double s[4][128];
    double a3 = 0.0, a4 = 0.0, a5 = 0.0, a6 = 0.0;
    for (int j = t; j < H_DIM; j += 128) {
        double ul = (double)g_uL[j], ur = (double)g_uR[j];
        double wl = (double)Wc[(size_t)h * 1024 + j];
        double wr = (double)Wc[(size_t)h * 1024 + 512 + j];
        a3 += wl * ul; a4 += wl * ur; a5 += wr * ul; a6 += wr * ur;
    }
    s[0][t] = a3; s[1][t] = a4; s[2][t] = a5; s[3][t] = a6;
    __syncthreads();
    for (int st = 64; st > 0; st >>= 1) {
        if (t < st)
            #pragma unroll
            for (int q = 0; q < 4; q++) s[q][t] += s[q][t + st];
        __syncthreads();
    }
    if (t == 0) {
        g_cols[0][h] = Wg[h];
        g_cols[1][h] = g_uL[h];
        g_cols[2][h] = g_uR[h];
        g_cols[3][h] = (float)s[0][0];
        g_cols[4][h] = (float)s[1][0];
        g_cols[5][h] = (float)s[2][0];
        g_cols[6][h] = (float)s[3][0];
    }
}

// GG[i][e] = sum_h Wp[e][h] * cols[i][h]   (gate vectors pushed through Wp)
__global__ void prep_g3(const float* __restrict__ Wp)
{
    const int e = blockIdx.x, t = threadIdx.x;
    __shared__ double s[7][128];
    double a[7] = {0, 0, 0, 0, 0, 0, 0};
    for (int h = t; h < H_DIM; h += 128) {
        double w = (double)Wp[(size_t)e * H_DIM + h];
        #pragma unroll
        for (int i = 0; i < 7; i++) a[i] += w * (double)g_cols[i][h];
    }
    #pragma unroll
    for (int i = 0; i < 7; i++) s[i][t] = a[i];
    __syncthreads();
    for (int st = 64; st > 0; st >>= 1) {
        if (t < st)
            #pragma unroll
            for (int i = 0; i < 7; i++) s[i][t] += s[i][t + st];
        __syncthreads();
    }
    if (t == 0)
        #pragma unroll
        for (int i = 0; i < 7; i++) g_GG[i][e] = (float)s[i][0];
}

// Scalar gate constants. One block, 256 threads. 16 dots then compose.
__global__ void prep_g4(const float* __restrict__ Wg, const float* __restrict__ bgp,
                        const float* __restrict__ dep, const float* __restrict__ bp)
{
    const int t = threadIdx.x;
    __shared__ double s[256];
    const float* pa[16] = { dep, dep + 512, dep + 1024, g_bL, g_bR,
                            g_bL, g_bL, g_bR, g_bR,
                            bp, bp, bp, bp, bp, bp, bp };
    const float* pb[16] = { Wg, Wg, Wg, Wg, Wg,
                            g_uL, g_uR, g_uL, g_uR,
                            g_cols[0], g_cols[1], g_cols[2], g_cols[3],
                            g_cols[4], g_cols[5], g_cols[6] };
    for (int d = 0; d < 16; d++) {
        double acc = 0.0;
        for (int c = t; c < H_DIM; c += 256)
            acc += (double)pa[d][c] * (double)pb[d][c];
        s[t] = acc;
        __syncthreads();
        for (int st = 128; st > 0; st >>= 1) {
            if (t < st) s[t] += s[t + st];
            __syncthreads();
        }
        if (t == 0) g_dots[d] = s[0];
        __syncthreads();
    }
    if (t == 0) {
        const double de = (double)DEPTH_EMBED_SCALE;
        double bg = (double)bgp[0];
        const double* d = g_dots;
        g_kc[0] = de * d[0] + bg + d[9];
        g_kc[1] = d[3] + de * d[1] + bg + d[10];
        g_kc[2] = d[4] + de * d[1] + bg + d[11];
        g_kc[3] = d[5] + d[3] + de * d[2] + bg + d[12];
        g_kc[4] = d[6] + d[4] + de * d[2] + bg + d[13];
        g_kc[5] = d[7] + d[3] + de * d[2] + bg + d[14];
        g_kc[6] = d[8] + d[4] + de * d[2] + bg + d[15];
    }
}

// ---------------------------------------------------------------------------
// tf32 tensor-core GEMM: C = A @ B + bias (+ sib). 128x128 tile, BK=16,
// 256 thr, 8 warps (2x4), warp tile 64x32, mma.m16n8k8.tf32, double-buffered
// cp.async. CVT=0: operands already tf32-rounded (skip cvt). RND=1: round
// outputs to tf32 on store. gather: A row indices.
// ---------------------------------------------------------------------------
#define AS_LD 20
#define BS_LD 136

template<int EPI, int CVT, int RND>
__global__ __launch_bounds__(256, 2)
void gemm_tf32(const float* __restrict__ A, const float* __restrict__ B,
               float* __restrict__ C, int M, int Ncol, int K,
               const float* __restrict__ bias, const float* __restrict__ sib,
               const int* __restrict__ gather)
{
    __shared__ float As[2][128][AS_LD];
    __shared__ float Bs[2][16][BS_LD];

    const int tid  = threadIdx.x;
    const int row0 = blockIdx.y * 128;
    const int col0 = blockIdx.x * 128;
    const int warp = tid >> 5, lane = tid & 31;
    const int gid  = lane >> 2, tg = lane & 3;
    const int wm   = (warp & 1) * 64;
    const int wn   = (warp >> 1) * 32;

    const int ar = tid >> 1;
    const int ak = (tid & 1) * 8;
    const int br = tid >> 4;
    const int bcg = (tid & 15) * 4;

    const float* Ag;
    {
        int r = row0 + ar;
        size_t rr = gather ? (size_t)gather[r] : (size_t)r;
        Ag = A + rr * (size_t)K + ak;
    }
    const float* Bg = B + (size_t)br * (size_t)Ncol + col0 + bcg;

    float acc[4][4][4];
    #pragma unroll
    for (int mi = 0; mi < 4; mi++)
        #pragma unroll
        for (int ni = 0; ni < 4; ni++)
            #pragma unroll
            for (int q = 0; q < 4; q++) acc[mi][ni][q] = 0.f;

    const int NT = K / 16;

    cp16(&As[0][ar][ak],     Ag);
    cp16(&As[0][ar][ak + 4], Ag + 4);
    cp16(&Bs[0][br][bcg],      Bg);
    cp16(&Bs[0][br][bcg + 64], Bg + 64);
    asm volatile("cp.async.commit_group;\n");

    for (int kt = 0; kt < NT; kt++) {
        const int cur = kt & 1;
        if (kt + 1 < NT) {
            const float* Agn = Ag + (size_t)(kt + 1) * 16;
            const float* Bgn = Bg + (size_t)(kt + 1) * 16 * (size_t)Ncol;
            cp16(&As[cur ^ 1][ar][ak],     Agn);
            cp16(&As[cur ^ 1][ar][ak + 4], Agn + 4);
            cp16(&Bs[cur ^ 1][br][bcg],      Bgn);
            cp16(&Bs[cur ^ 1][br][bcg + 64], Bgn + 64);
            asm volatile("cp.async.commit_group;\n");
            asm volatile("cp.async.wait_group 1;\n");
        } else {
            asm volatile("cp.async.wait_group 0;\n");
        }
        __syncthreads();

        #pragma unroll
        for (int ks = 0; ks < 2; ks++) {
            const int kk = ks * 8;
            uint32_t af[4][4];
            #pragma unroll
            for (int mi = 0; mi < 4; mi++) {
                int r = wm + mi * 16 + gid;
                float x0 = As[cur][r    ][kk + tg];
                float x1 = As[cur][r + 8][kk + tg];
                float x2 = As[cur][r    ][kk + tg + 4];
                float x3 = As[cur][r + 8][kk + tg + 4];
                af[mi][0] = CVT ? f2tf32(x0) : __float_as_uint(x0);
                af[mi][1] = CVT ? f2tf32(x1) : __float_as_uint(x1);
                af[mi][2] = CVT ? f2tf32(x2) : __float_as_uint(x2);
                af[mi][3] = CVT ? f2tf32(x3) : __float_as_uint(x3);
            }
            uint32_t bf[4][2];
            #pragma unroll
            for (int ni = 0; ni < 4; ni++) {
                int cc = wn + ni * 8 + gid;
                float y0 = Bs[cur][kk + tg    ][cc];
                float y1 = Bs[cur][kk + tg + 4][cc];
                bf[ni][0] = CVT ? f2tf32(y0) : __float_as_uint(y0);
                bf[ni][1] = CVT ? f2tf32(y1) : __float_as_uint(y1);
            }
            #pragma unroll
            for (int mi = 0; mi < 4; mi++)
                #pragma unroll
                for (int ni = 0; ni < 4; ni++) {
                    asm volatile(
                        "mma.sync.aligned.m16n8k8.row.col.f32.tf32.tf32.f32 "
                        "{%0,%1,%2,%3}, {%4,%5,%6,%7}, {%8,%9}, {%0,%1,%2,%3};"
                        : "+f"(acc[mi][ni][0]), "+f"(acc[mi][ni][1]),
                          "+f"(acc[mi][ni][2]), "+f"(acc[mi][ni][3])
                        : "r"(af[mi][0]), "r"(af[mi][1]), "r"(af[mi][2]), "r"(af[mi][3]),
                          "r"(bf[ni][0]), "r"(bf[ni][1]));
                }
        }
        __syncthreads();
    }

    #pragma unroll
    for (int ni = 0; ni < 4; ni++) {
        int cc = col0 + wn + ni * 8 + tg * 2;
        float b0 = bias[cc], b1 = bias[cc + 1];
        if (EPI == 1) { b0 += SIB_SCALE_F * sib[cc]; b1 += SIB_SCALE_F * sib[cc + 1]; }
        #pragma unroll
        for (int mi = 0; mi < 4; mi++) {
            int r = row0 + wm + mi * 16 + gid;
            float v0 = acc[mi][ni][0] + b0, v1 = acc[mi][ni][1] + b1;
            float v2 = acc[mi][ni][2] + b0, v3 = acc[mi][ni][3] + b1;
            if (RND) { v0 = rtf(v0); v1 = rtf(v1); v2 = rtf(v2); v3 = rtf(v3); }
            *(float2*)(C + (size_t)r * (size_t)Ncol + cc)       = make_float2(v0, v1);
            *(float2*)(C + (size_t)(r + 8) * (size_t)Ncol + cc) = make_float2(v2, v3);
        }
    }
}

// ---------------------------------------------------------------------------
// Gate + pool kernel. Gates = emb[tok] . GG_i + k_i (double accumulation,
// closest to exact -> minimal flip risk vs reference fp32).
// ---------------------------------------------------------------------------
__global__ __launch_bounds__(256)
void pool_kernel(const int* __restrict__ tokens, const float* __restrict__ emb,
                 float* __restrict__ pooled)
{
    const int n = blockIdx.x;
    const int t = threadIdx.x;
    const float* a  = emb + (size_t)tokens[n] * H_DIM;
    const float* H0 = g_h0 + (size_t)n * H_DIM;
    const float* C1 = g_c1 + (size_t)n * (2 * H_DIM);
    const float* C2 = g_c2 + (size_t)n * (4 * H_DIM);
    const float* D3 = g_d3 + (size_t)n * (4 * H_DIM);

    __shared__ double red[7][256];
    double p[7] = {0, 0, 0, 0, 0, 0, 0};
    for (int c = t; c < H_DIM; c += 256) {
        double av = (double)a[c];
        #pragma unroll
        for (int i = 0; i < 7; i++) p[i] += av * (double)g_GG[i][c];
    }
    #pragma unroll
    for (int i = 0; i < 7; i++) red[i][t] = p[i];
    __syncthreads();
    for (int s = 128; s > 0; s >>= 1) {
        if (t < s)
            #pragma unroll
            for (int i = 0; i < 7; i++) red[i][t] += red[i][t + s];
        __syncthreads();
    }

    const bool e0 = (red[0][0] + g_kc[0]) > 0.0;
    bool e1[2], e2[4];
    e1[0] = e0 && ((red[1][0] + g_kc[1]) > 0.0);
    e1[1] = e0 && ((red[2][0] + g_kc[2]) > 0.0);
    e2[0] = e1[0] && ((red[3][0] + g_kc[3]) > 0.0);
    e2[1] = e1[0] && ((red[4][0] + g_kc[4]) > 0.0);
    e2[2] = e1[1] && ((red[5][0] + g_kc[5]) > 0.0);
    e2[3] = e1[1] && ((red[6][0] + g_kc[6]) > 0.0);

    float count = 1.f
        + 2.f * (e0 ? 1.f : 0.f)
        + 2.f * ((e1[0] ? 1.f : 0.f) + (e1[1] ? 1.f : 0.f))
        + 2.f * ((e2[0] ? 1.f : 0.f) + (e2[1] ? 1.f : 0.f) +
                 (e2[2] ? 1.f : 0.f) + (e2[3] ? 1.f : 0.f));
    const float inv = 1.f / fmaxf(count, 1e-8f);

    for (int c = t; c < H_DIM; c += 256) {
        float s = H0[c];
        if (e0)    s += C1[c] + C1[H_DIM + c];
        if (e1[0]) s += C2[c] + C2[H_DIM + c];
        if (e1[1]) s += C2[2 * H_DIM + c] + C2[3 * H_DIM + c];
        if (e2[0]) s += D3[0 * H_DIM + c];
        if (e2[1]) s += D3[1 * H_DIM + c];
        if (e2[2]) s += D3[2 * H_DIM + c];
        if (e2[3]) s += D3[3 * H_DIM + c];
        pooled[(size_t)n * H_DIM + c] = rtf(s * inv);   // pre-rounded for CVT=0 GEMM
    }
}

// ---------------------------------------------------------------------------
extern "C" void kernel_launch(void* const* d_in, const int* in_sizes, int n_in,
                              void* d_out, int out_size)
{
    const int*   tokens = (const int*)  d_in[0];
    const float* emb    = (const float*)d_in[1];
    const float* Wp     = (const float*)d_in[2];
    const float* bp     = (const float*)d_in[3];
    const float* Wc     = (const float*)d_in[4];
    const float* bc     = (const float*)d_in[5];
    const float* Wg     = (const float*)d_in[6];
    const float* bg     = (const float*)d_in[7];
    const float* dep    = (const float*)d_in[8];
    const float* sib    = (const float*)d_in[9];
    const float* Wout   = (const float*)d_in[10];
    const float* bout   = (const float*)d_in[11];
    float* out = (float*)d_out;

    float *h0, *c1, *c2, *d3, *pooled, *W2, *b2, *Wc_r, *Wout_r;
    cudaGetSymbolAddress((void**)&h0,     g_h0);
    cudaGetSymbolAddress((void**)&c1,     g_c1);
    cudaGetSymbolAddress((void**)&c2,     g_c2);
    cudaGetSymbolAddress((void**)&d3,     g_d3);
    cudaGetSymbolAddress((void**)&pooled, g_pooled);
    cudaGetSymbolAddress((void**)&W2,     g_W2);
    cudaGetSymbolAddress((void**)&b2,     g_b2);
    cudaGetSymbolAddress((void**)&Wc_r,   g_Wc_r);
    cudaGetSymbolAddress((void**)&Wout_r, g_Wout_r);

    dim3 blk(256);

    // Prep: rounded weight copies + gate composite vectors/constants
    round_tf32_k<<<(H_DIM * V_DIM / 4 + 255) / 256, blk>>>(Wout, Wout_r, H_DIM * V_DIM / 4);
    round_tf32_k<<<(H_DIM * 1024 / 4 + 255) / 256, blk>>>(Wc, Wc_r, H_DIM * 1024 / 4);
    prep_w2<<<(H_DIM * H_DIM) / 256, blk>>>(Wc, bc, sib);
    prep_g1<<<H_DIM, 128>>>(Wc, Wg, bc, sib);
    prep_g2<<<H_DIM, 128>>>(Wc, Wg);
    prep_g3<<<H_DIM, 128>>>(Wp);
    prep_g4<<<1, blk>>>(Wg, bg, dep, bp);

    // h0 = emb[tokens] @ Wp + bp   (tf32, gathered A, round output)
    gemm_tf32<0, 1, 1><<<dim3(H_DIM / 128, N_TOK / 128), blk>>>(
        emb, Wp, h0, N_TOK, H_DIM, H_DIM, bp, nullptr, tokens);

    // c1 = h0 @ Wc + bc + SIB*sib
    gemm_tf32<1, 0, 1><<<dim3(1024 / 128, N_TOK / 128), blk>>>(
        h0, Wc_r, c1, N_TOK, 1024, H_DIM, bc, sib, nullptr);

    // c2 = c1 @ Wc + bc + SIB*sib
    gemm_tf32<1, 0, 1><<<dim3(1024 / 128, (2 * N_TOK) / 128), blk>>>(
        c1, Wc_r, c2, 2 * N_TOK, 1024, H_DIM, bc, sib, nullptr);

    // d3 = c2 @ W2 + b2   (depth-3 pair sums)
    gemm_tf32<0, 0, 0><<<dim3(H_DIM / 128, (4 * N_TOK) / 128), blk>>>(
        c2, W2, d3, 4 * N_TOK, H_DIM, H_DIM, b2, nullptr, nullptr);

    // gates (composite, double) + masked pooling + tf32-round pooled
    pool_kernel<<<N_TOK, blk>>>(tokens, emb, pooled);

    // logits = pooled @ Wout + bout  (pre-rounded operands, no in-loop cvt)
    gemm_tf32<0, 0, 0><<<dim3(V_DIM / 128, N_TOK / 128), blk>>>(
        pooled, Wout_r, out, N_TOK, V_DIM, H_DIM, bout, nullptr, nullptr);
}

// round 8
// speedup vs baseline: 4.4527x; 1.5706x over previous
#include <cuda_runtime.h>
#include <cuda_fp16.h>
#include <cstdint>

// Problem constants (B=8, S=512 -> N=4096 tokens)
#define N_TOK   4096
#define H_DIM   512
#define V_DIM   32000
#define DEPTH_EMBED_SCALE 0.01f
#define SIB_SCALE_F 0.04419417382415922f   // (float)(1/sqrt(512))

// Scratch (no allocations -> __device__ globals)
__device__ float  g_h0[N_TOK * H_DIM];
__device__ float  g_c1[N_TOK * 2 * H_DIM];
__device__ float  g_c2[N_TOK * 4 * H_DIM];
__device__ float  g_d3[N_TOK * 4 * H_DIM];       // depth-3 pair sums = c2 @ W2 + b2
__device__ __half g_h0h[N_TOK * H_DIM];
__device__ __half g_c1h[N_TOK * 2 * H_DIM];
__device__ __half g_c2h[N_TOK * 4 * H_DIM];
__device__ __half g_pooled_h[N_TOK * H_DIM];
__device__ __half g_A0h[N_TOK * H_DIM];          // gathered emb rows (fp16)
__device__ __half g_Wp_h[H_DIM * H_DIM];
__device__ __half g_Wc_h[H_DIM * 1024];
__device__ __half g_W2h[H_DIM * H_DIM];          // fp16(WcL + WcR)
__device__ __half g_Wout_h[H_DIM * V_DIM];
__device__ float  g_b2[H_DIM];
// Gate composite precompute
__device__ float  g_uL[H_DIM], g_uR[H_DIM], g_bL[H_DIM], g_bR[H_DIM];
__device__ float  g_cols[7][H_DIM];              // gate vectors in h0-space
__device__ float  g_GG[7][H_DIM];                // gate vectors in emb-space
__device__ double g_kc[7];
__device__ double g_dots[16];

__device__ __forceinline__ void cp16(void* s, const void* g) {
    unsigned saddr = (unsigned)__cvta_generic_to_shared(s);
    asm volatile("cp.async.cg.shared.global [%0], [%1], 16;\n" :: "r"(saddr), "l"(g));
}

// ---------------------------------------------------------------------------
// Prep kernels
// ---------------------------------------------------------------------------
__global__ void cvt_f16_k(const float* __restrict__ src, __half* __restrict__ dst, int n8)
{
    int i = blockIdx.x * 256 + threadIdx.x;
    if (i < n8) {
        float4 a = ((const float4*)src)[2 * i];
        float4 b = ((const float4*)src)[2 * i + 1];
        __half2 h0 = __floats2half2_rn(a.x, a.y);
        __half2 h1 = __floats2half2_rn(a.z, a.w);
        __half2 h2 = __floats2half2_rn(b.x, b.y);
        __half2 h3 = __floats2half2_rn(b.z, b.w);
        uint4 o;
        o.x = *(uint32_t*)&h0; o.y = *(uint32_t*)&h1;
        o.z = *(uint32_t*)&h2; o.w = *(uint32_t*)&h3;
        ((uint4*)dst)[i] = o;
    }
}

__global__ void gather_emb_f16(const int* __restrict__ tokens, const float* __restrict__ emb)
{
    int i = blockIdx.x * 256 + threadIdx.x;      // over N_TOK*H_DIM/8
    int n = i >> 6;                              // 64 chunks of 8 per row
    int c = (i & 63) * 8;
    const float* src = emb + (size_t)tokens[n] * H_DIM + c;
    float4 a = *(const float4*)src;
    float4 b = *(const float4*)(src + 4);
    __half2 h0 = __floats2half2_rn(a.x, a.y);
    __half2 h1 = __floats2half2_rn(a.z, a.w);
    __half2 h2 = __floats2half2_rn(b.x, b.y);
    __half2 h3 = __floats2half2_rn(b.z, b.w);
    uint4 o;
    o.x = *(uint32_t*)&h0; o.y = *(uint32_t*)&h1;
    o.z = *(uint32_t*)&h2; o.w = *(uint32_t*)&h3;
    ((uint4*)(g_A0h + (size_t)n * H_DIM + c))[0] = o;
}

__global__ void prep_w2(const float* __restrict__ Wc, const float* __restrict__ bc,
                        const float* __restrict__ sib)
{
    int i = blockIdx.x * 256 + threadIdx.x;   // 0 .. 512*512-1
    int h = i >> 9, j = i & 511;
    g_W2h[i] = __float2half_rn(Wc[(size_t)h * 1024 + j] + Wc[(size_t)h * 1024 + 512 + j]);
    if (i < H_DIM)
        g_b2[i] = bc[i] + bc[512 + i] + SIB_SCALE_F * (sib[i] + sib[512 + i]);
}

// uL = WcL@Wg, uR = WcR@Wg; bL/bR vectors.
__global__ void prep_g1(const float* __restrict__ Wc, const float* __restrict__ Wg,
                        const float* __restrict__ bc, const float* __restrict__ sib)
{
    const int h = blockIdx.x, t = threadIdx.x;
    __shared__ double s[2][128];
    double aL = 0.0, aR = 0.0;
    for (int j = t; j < H_DIM; j += 128) {
        double w = (double)Wg[j];
        aL += (double)Wc[(size_t)h * 1024 + j]       * w;
        aR += (double)Wc[(size_t)h * 1024 + 512 + j] * w;
    }
    s[0][t] = aL; s[1][t] = aR;
    __syncthreads();
    for (int st = 64; st > 0; st >>= 1) {
        if (t < st) { s[0][t] += s[0][t + st]; s[1][t] += s[1][t + st]; }
        __syncthreads();
    }
    if (t == 0) {
        g_uL[h] = (float)s[0][0];
        g_uR[h] = (float)s[1][0];
        g_bL[h] = bc[h]       + SIB_SCALE_F * sib[h];
        g_bR[h] = bc[512 + h] + SIB_SCALE_F * sib[512 + h];
    }
}

__global__ void prep_g2(const float* __restrict__ Wc, const float* __restrict__ Wg)
{
    const int h = blockIdx.x, t = threadIdx.x;
    __shared__ double s[4][128];
    double a3 = 0.0, a4 = 0.0, a5 = 0.0, a6 = 0.0;
    for (int j = t; j < H_DIM; j += 128) {
        double ul = (double)g_uL[j], ur = (double)g_uR[j];
        double wl = (double)Wc[(size_t)h * 1024 + j];
        double wr = (double)Wc[(size_t)h * 1024 + 512 + j];
        a3 += wl * ul; a4 += wl * ur; a5 += wr * ul; a6 += wr * ur;
    }
    s[0][t] = a3; s[1][t] = a4; s[2][t] = a5; s[3][t] = a6;
    __syncthreads();
    for (int st = 64; st > 0; st >>= 1) {
        if (t < st)
            #pragma unroll
            for (int q = 0; q < 4; q++) s[q][t] += s[q][t + st];
        __syncthreads();
    }
    if (t == 0) {
        g_cols[0][h] = Wg[h];
        g_cols[1][h] = g_uL[h];
        g_cols[2][h] = g_uR[h];
        g_cols[3][h] = (float)s[0][0];
        g_cols[4][h] = (float)s[1][0];
        g_cols[5][h] = (float)s[2][0];
        g_cols[6][h] = (float)s[3][0];
    }
}

__global__ void prep_g3(const float* __restrict__ Wp)
{
    const int e = blockIdx.x, t = threadIdx.x;
    __shared__ double s[7][128];
    double a[7] = {0, 0, 0, 0, 0, 0, 0};
    for (int h = t; h < H_DIM; h += 128) {
        double w = (double)Wp[(size_t)e * H_DIM + h];
        #pragma unroll
        for (int i = 0; i < 7; i++) a[i] += w * (double)g_cols[i][h];
    }
    #pragma unroll
    for (int i = 0; i < 7; i++) s[i][t] = a[i];
    __syncthreads();
    for (int st = 64; st > 0; st >>= 1) {
        if (t < st)
            #pragma unroll
            for (int i = 0; i < 7; i++) s[i][t] += s[i][t + st];
        __syncthreads();
    }
    if (t == 0)
        #pragma unroll
        for (int i = 0; i < 7; i++) g_GG[i][e] = (float)s[i][0];
}

__global__ void prep_g4(const float* __restrict__ Wg, const float* __restrict__ bgp,
                        const float* __restrict__ dep, const float* __restrict__ bp)
{
    const int t = threadIdx.x;
    __shared__ double s[256];
    const float* pa[16] = { dep, dep + 512, dep + 1024, g_bL, g_bR,
                            g_bL, g_bL, g_bR, g_bR,
                            bp, bp, bp, bp, bp, bp, bp };
    const float* pb[16] = { Wg, Wg, Wg, Wg, Wg,
                            g_uL, g_uR, g_uL, g_uR,
                            g_cols[0], g_cols[1], g_cols[2], g_cols[3],
                            g_cols[4], g_cols[5], g_cols[6] };
    for (int d = 0; d < 16; d++) {
        double acc = 0.0;
        for (int c = t; c < H_DIM; c += 256)
            acc += (double)pa[d][c] * (double)pb[d][c];
        s[t] = acc;
        __syncthreads();
        for (int st = 128; st > 0; st >>= 1) {
            if (t < st) s[t] += s[t + st];
            __syncthreads();
        }
        if (t == 0) g_dots[d] = s[0];
        __syncthreads();
    }
    if (t == 0) {
        const double de = (double)DEPTH_EMBED_SCALE;
        double bg = (double)bgp[0];
        const double* d = g_dots;
        g_kc[0] = de * d[0] + bg + d[9];
        g_kc[1] = d[3] + de * d[1] + bg + d[10];
        g_kc[2] = d[4] + de * d[1] + bg + d[11];
        g_kc[3] = d[5] + d[3] + de * d[2] + bg + d[12];
        g_kc[4] = d[6] + d[4] + de * d[2] + bg + d[13];
        g_kc[5] = d[7] + d[3] + de * d[2] + bg + d[14];
        g_kc[6] = d[8] + d[4] + de * d[2] + bg + d[15];
    }
}

// ---------------------------------------------------------------------------
// fp16 tensor-core GEMM: C = A @ B + bias (+ sib). 128x128 tile, BK=32,
// 256 thr, 8 warps (2x4), warp tile 64x32, mma.m16n8k16.f16 (f32 accum),
// ldmatrix fragment loads, double-buffered cp.async.
// A: fp16 row-major [M][K]; B: fp16 row-major [K][Ncol].
// WF16=1: additionally store fp16 copy of C to C16 (for GEMM chaining).
// ---------------------------------------------------------------------------
#define AS_LD 40     // 32 + 8 pad (halfs) -> 80B row stride, conflict-free LDSM
#define BS_LD 136    // 128 + 8 pad (halfs) -> 272B row stride, conflict-free LDSM

#define LDSM_X4(r0, r1, r2, r3, addr) \
    asm volatile("ldmatrix.sync.aligned.m8n8.x4.shared.b16 {%0,%1,%2,%3}, [%4];" \
        : "=r"(r0), "=r"(r1), "=r"(r2), "=r"(r3) : "r"(addr))
#define LDSM_X4T(r0, r1, r2, r3, addr) \
    asm volatile("ldmatrix.sync.aligned.m8n8.x4.trans.shared.b16 {%0,%1,%2,%3}, [%4];" \
        : "=r"(r0), "=r"(r1), "=r"(r2), "=r"(r3) : "r"(addr))

template<int EPI, int WF16>
__global__ __launch_bounds__(256, 2)
void gemm_f16(const __half* __restrict__ A, const __half* __restrict__ B,
              float* __restrict__ C, __half* __restrict__ C16,
              int M, int Ncol, int K,
              const float* __restrict__ bias, const float* __restrict__ sib)
{
    __shared__ __half As[2][128][AS_LD];
    __shared__ __half Bs[2][32][BS_LD];

    const int tid  = threadIdx.x;
    const int row0 = blockIdx.y * 128;
    const int col0 = blockIdx.x * 128;
    const int warp = tid >> 5, lane = tid & 31;
    const int gid  = lane >> 2, tg = lane & 3;
    const int wm   = (warp & 1) * 64;
    const int wn   = (warp >> 1) * 32;

    // cp.async mappings
    const int ar = tid >> 1;             // A row 0..127
    const int ac = (tid & 1) * 16;       // A col base (halfs): two 16B chunks
    const int br = tid >> 3;             // B k-row 0..31
    const int bc = (tid & 7) * 16;       // B col base (halfs): two 16B chunks

    const __half* Ag = A + (size_t)(row0 + ar) * (size_t)K + ac;
    const __half* Bg = B + (size_t)br * (size_t)Ncol + col0 + bc;

    // ldmatrix per-lane address components
    const int a_r = lane & 15;                 // row within 16
    const int a_c = (lane >> 4) << 3;          // k offset 0/8
    const int b_k = (lane & 7) + (lane & 8);   // k row within 16
    const int b_c = (lane >> 4) << 3;          // n offset 0/8

    const uint32_t as_base = (uint32_t)__cvta_generic_to_shared(&As[0][0][0]);
    const uint32_t bs_base = (uint32_t)__cvta_generic_to_shared(&Bs[0][0][0]);
    const uint32_t AS_STG = 128 * AS_LD * 2;   // bytes per stage
    const uint32_t BS_STG = 32 * BS_LD * 2;

    float acc[4][4][4];
    #pragma unroll
    for (int mi = 0; mi < 4; mi++)
        #pragma unroll
        for (int ni = 0; ni < 4; ni++)
            #pragma unroll
            for (int q = 0; q < 4; q++) acc[mi][ni][q] = 0.f;

    const int NT = K / 32;

    cp16(&As[0][ar][ac],     Ag);
    cp16(&As[0][ar][ac + 8], Ag + 8);
    cp16(&Bs[0][br][bc],     Bg);
    cp16(&Bs[0][br][bc + 8], Bg + 8);
    asm volatile("cp.async.commit_group;\n");

    for (int kt = 0; kt < NT; kt++) {
        const int cur = kt & 1;
        if (kt + 1 < NT) {
            const __half* Agn = Ag + (size_t)(kt + 1) * 32;
            const __half* Bgn = Bg + (size_t)(kt + 1) * 32 * (size_t)Ncol;
            cp16(&As[cur ^ 1][ar][ac],     Agn);
            cp16(&As[cur ^ 1][ar][ac + 8], Agn + 8);
            cp16(&Bs[cur ^ 1][br][bc],     Bgn);
            cp16(&Bs[cur ^ 1][br][bc + 8], Bgn + 8);
            asm volatile("cp.async.commit_group;\n");
            asm volatile("cp.async.wait_group 1;\n");
        } else {
            asm volatile("cp.async.wait_group 0;\n");
        }
        __syncthreads();

        const uint32_t asb = as_base + cur * AS_STG;
        const uint32_t bsb = bs_base + cur * BS_STG;

        #pragma unroll
        for (int ks = 0; ks < 2; ks++) {
            const int kk = ks * 16;
            uint32_t af[4][4];
            #pragma unroll
            for (int mi = 0; mi < 4; mi++) {
                uint32_t ad = asb + ((wm + mi * 16 + a_r) * AS_LD + kk + a_c) * 2;
                LDSM_X4(af[mi][0], af[mi][1], af[mi][2], af[mi][3], ad);
            }
            uint32_t bf[4][2];
            #pragma unroll
            for (int j = 0; j < 2; j++) {
                uint32_t bd = bsb + ((kk + b_k) * BS_LD + wn + j * 16 + b_c) * 2;
                LDSM_X4T(bf[2 * j][0], bf[2 * j][1], bf[2 * j + 1][0], bf[2 * j + 1][1], bd);
            }
            #pragma unroll
            for (int mi = 0; mi < 4; mi++)
                #pragma unroll
                for (int ni = 0; ni < 4; ni++) {
                    asm volatile(
                        "mma.sync.aligned.m16n8k16.row.col.f32.f16.f16.f32 "
                        "{%0,%1,%2,%3}, {%4,%5,%6,%7}, {%8,%9}, {%0,%1,%2,%3};"
                        : "+f"(acc[mi][ni][0]), "+f"(acc[mi][ni][1]),
                          "+f"(acc[mi][ni][2]), "+f"(acc[mi][ni][3])
                        : "r"(af[mi][0]), "r"(af[mi][1]), "r"(af[mi][2]), "r"(af[mi][3]),
                          "r"(bf[ni][0]), "r"(bf[ni][1]));
                }
        }
        __syncthreads();
    }

    #pragma unroll
    for (int ni = 0; ni < 4; ni++) {
        int cc = col0 + wn + ni * 8 + tg * 2;
        float b0 = bias[cc], b1 = bias[cc + 1];
        if (EPI == 1) { b0 += SIB_SCALE_F * sib[cc]; b1 += SIB_SCALE_F * sib[cc + 1]; }
        #pragma unroll
        for (int mi = 0; mi < 4; mi++) {
            int r = row0 + wm + mi * 16 + gid;
            float v0 = acc[mi][ni][0] + b0, v1 = acc[mi][ni][1] + b1;
            float v2 = acc[mi][ni][2] + b0, v3 = acc[mi][ni][3] + b1;
            *(float2*)(C + (size_t)r * (size_t)Ncol + cc)       = make_float2(v0, v1);
            *(float2*)(C + (size_t)(r + 8) * (size_t)Ncol + cc) = make_float2(v2, v3);
            if (WF16) {
                *(__half2*)(C16 + (size_t)r * (size_t)Ncol + cc)       = __floats2half2_rn(v0, v1);
                *(__half2*)(C16 + (size_t)(r + 8) * (size_t)Ncol + cc) = __floats2half2_rn(v2, v3);
            }
        }
    }
}

// ---------------------------------------------------------------------------
// Gate + pool kernel. Gates = emb[tok] . GG_i + k_i (double accumulation).
// Pool sums fp32 node values; writes pooled as fp16 (big-GEMM A operand).
// ---------------------------------------------------------------------------
__global__ __launch_bounds__(256)
void pool_kernel(const int* __restrict__ tokens, const float* __restrict__ emb)
{
    const int n = blockIdx.x;
    const int t = threadIdx.x;
    const float* a  = emb + (size_t)tokens[n] * H_DIM;
    const float* H0 = g_h0 + (size_t)n * H_DIM;
    const float* C1 = g_c1 + (size_t)n * (2 * H_DIM);
    const float* C2 = g_c2 + (size_t)n * (4 * H_DIM);
    const float* D3 = g_d3 + (size_t)n * (4 * H_DIM);

    __shared__ double red[7][256];
    double p[7] = {0, 0, 0, 0, 0, 0, 0};
    for (int c = t; c < H_DIM; c += 256) {
        double av = (double)a[c];
        #pragma unroll
        for (int i = 0; i < 7; i++) p[i] += av * (double)g_GG[i][c];
    }
    #pragma unroll
    for (int i = 0; i < 7; i++) red[i][t] = p[i];
    __syncthreads();
    for (int s = 128; s > 0; s >>= 1) {
        if (t < s)
            #pragma unroll
            for (int i = 0; i < 7; i++) red[i][t] += red[i][t + s];
        __syncthreads();
    }

    const bool e0 = (red[0][0] + g_kc[0]) > 0.0;
    bool e1[2], e2[4];
    e1[0] = e0 && ((red[1][0] + g_kc[1]) > 0.0);
    e1[1] = e0 && ((red[2][0] + g_kc[2]) > 0.0);
    e2[0] = e1[0] && ((red[3][0] + g_kc[3]) > 0.0);
    e2[1] = e1[0] && ((red[4][0] + g_kc[4]) > 0.0);
    e2[2] = e1[1] && ((red[5][0] + g_kc[5]) > 0.0);
    e2[3] = e1[1] && ((red[6][0] + g_kc[6]) > 0.0);

    float count = 1.f
        + 2.f * (e0 ? 1.f : 0.f)
        + 2.f * ((e1[0] ? 1.f : 0.f) + (e1[1] ? 1.f : 0.f))
        + 2.f * ((e2[0] ? 1.f : 0.f) + (e2[1] ? 1.f : 0.f) +
                 (e2[2] ? 1.f : 0.f) + (e2[3] ? 1.f : 0.f));
    const float inv = 1.f / fmaxf(count, 1e-8f);

    for (int c = t; c < H_DIM; c += 256) {
        float s = H0[c];
        if (e0)    s += C1[c] + C1[H_DIM + c];
        if (e1[0]) s += C2[c] + C2[H_DIM + c];
        if (e1[1]) s += C2[2 * H_DIM + c] + C2[3 * H_DIM + c];
        if (e2[0]) s += D3[0 * H_DIM + c];
        if (e2[1]) s += D3[1 * H_DIM + c];
        if (e2[2]) s += D3[2 * H_DIM + c];
        if (e2[3]) s += D3[3 * H_DIM + c];
        g_pooled_h[(size_t)n * H_DIM + c] = __float2half_rn(s * inv);
    }
}

// ---------------------------------------------------------------------------
extern "C" void kernel_launch(void* const* d_in, const int* in_sizes, int n_in,
                              void* d_out, int out_size)
{
    const int*   tokens = (const int*)  d_in[0];
    const float* emb    = (const float*)d_in[1];
    const float* Wp     = (const float*)d_in[2];
    const float* bp     = (const float*)d_in[3];
    const float* Wc     = (const float*)d_in[4];
    const float* bc     = (const float*)d_in[5];
    const float* Wg     = (const float*)d_in[6];
    const float* bg     = (const float*)d_in[7];
    const float* dep    = (const float*)d_in[8];
    const float* sib    = (const float*)d_in[9];
    const float* Wout   = (const float*)d_in[10];
    const float* bout   = (const float*)d_in[11];
    float* out = (float*)d_out;

    float  *h0, *c1, *c2, *d3, *b2;
    __half *h0h, *c1h, *c2h, *pooledh, *A0h, *Wp_h, *Wc_h, *W2h, *Wout_h;
    cudaGetSymbolAddress((void**)&h0,      g_h0);
    cudaGetSymbolAddress((void**)&c1,      g_c1);
    cudaGetSymbolAddress((void**)&c2,      g_c2);
    cudaGetSymbolAddress((void**)&d3,      g_d3);
    cudaGetSymbolAddress((void**)&b2,      g_b2);
    cudaGetSymbolAddress((void**)&h0h,     g_h0h);
    cudaGetSymbolAddress((void**)&c1h,     g_c1h);
    cudaGetSymbolAddress((void**)&c2h,     g_c2h);
    cudaGetSymbolAddress((void**)&pooledh, g_pooled_h);
    cudaGetSymbolAddress((void**)&A0h,     g_A0h);
    cudaGetSymbolAddress((void**)&Wp_h,    g_Wp_h);
    cudaGetSymbolAddress((void**)&Wc_h,    g_Wc_h);
    cudaGetSymbolAddress((void**)&W2h,     g_W2h);
    cudaGetSymbolAddress((void**)&Wout_h,  g_Wout_h);

    dim3 blk(256);

    // Weight conversions + gather + gate composite
    cvt_f16_k<<<(H_DIM * V_DIM / 8 + 255) / 256, blk>>>(Wout, Wout_h, H_DIM * V_DIM / 8);
    cvt_f16_k<<<(H_DIM * 1024 / 8 + 255) / 256, blk>>>(Wc, Wc_h, H_DIM * 1024 / 8);
    cvt_f16_k<<<(H_DIM * H_DIM / 8 + 255) / 256, blk>>>(Wp, Wp_h, H_DIM * H_DIM / 8);
    prep_w2<<<(H_DIM * H_DIM) / 256, blk>>>(Wc, bc, sib);
    gather_emb_f16<<<(N_TOK * H_DIM / 8) / 256, blk>>>(tokens, emb);
    prep_g1<<<H_DIM, 128>>>(Wc, Wg, bc, sib);
    prep_g2<<<H_DIM, 128>>>(Wc, Wg);
    prep_g3<<<H_DIM, 128>>>(Wp);
    prep_g4<<<1, blk>>>(Wg, bg, dep, bp);

    // h0 = emb[tokens] @ Wp + bp
    gemm_f16<0, 1><<<dim3(H_DIM / 128, N_TOK / 128), blk>>>(
        A0h, Wp_h, h0, h0h, N_TOK, H_DIM, H_DIM, bp, nullptr);

    // c1 = h0 @ Wc + bc + SIB*sib
    gemm_f16<1, 1><<<dim3(1024 / 128, N_TOK / 128), blk>>>(
        h0h, Wc_h, c1, c1h, N_TOK, 1024, H_DIM, bc, sib);

    // c2 = c1 @ Wc + bc + SIB*sib
    gemm_f16<1, 1><<<dim3(1024 / 128, (2 * N_TOK) / 128), blk>>>(
        c1h, Wc_h, c2, c2h, 2 * N_TOK, 1024, H_DIM, bc, sib);

    // d3 = c2 @ W2 + b2   (depth-3 pair sums, f32 out only)
    gemm_f16<0, 0><<<dim3(H_DIM / 128, (4 * N_TOK) / 128), blk>>>(
        c2h, W2h, d3, nullptr, 4 * N_TOK, H_DIM, H_DIM, b2, nullptr);

    // gates (composite, double) + masked pooling -> fp16 pooled
    pool_kernel<<<N_TOK, blk>>>(tokens, emb);

    // logits = pooled @ Wout + bout   (4096 x 32000 x 512, fp16 tensor cores)
    gemm_f16<0, 0><<<dim3(V_DIM / 128, N_TOK / 128), blk>>>(
        pooledh, Wout_h, out, nullptr, N_TOK, V_DIM, H_DIM, bout, nullptr);
}